// round 12
// baseline (speedup 1.0000x reference)
#include <cuda_runtime.h>
#include <cuda_fp16.h>
#include <math.h>
#include <stdint.h>

#define N_TOK 12288
#define DIMC  768
#define HEADS 12
#define HD    64
#define NWIN  192
#define BATCH 2
#define M_ROWS (BATCH * N_TOK)   // 24576
#define SHIFT 32
#define SCALE 0.125f

// ---------------- scratch (device globals) ---------------------------------
__device__ __half g_big[M_ROWS * 4 * DIMC];   // qkv scratch, later MLP hidden
__device__ __half g_hs [M_ROWS * DIMC];       // LN outputs (fp16)
__device__ __half g_o  [M_ROWS * DIMC];       // attention out (fp16)
__device__ float  g_x2 [M_ROWS * DIMC];       // x + proj residual (fp32)
__device__ float  g_bias[HEADS * 64 * 64];    // precomputed rel-pos bias
#define W_QKV 0
#define W_PROJ (W_QKV + 3 * DIMC * DIMC)
#define W_FC1  (W_PROJ + DIMC * DIMC)
#define W_FC2  (W_FC1 + 4 * DIMC * DIMC)
#define W_TOT  (W_FC2 + 4 * DIMC * DIMC)
__device__ __half g_wt[W_TOT];

// ---------------- helpers ---------------------------------------------------
__device__ __forceinline__ void cp16(uint32_t dst, const void* src) {
    asm volatile("cp.async.cg.shared.global [%0], [%1], 16;\n" :: "r"(dst), "l"(src));
}
__device__ __forceinline__ void ldsm4(uint32_t& r0, uint32_t& r1,
                                      uint32_t& r2, uint32_t& r3, uint32_t a) {
    asm volatile("ldmatrix.sync.aligned.m8n8.x4.shared.b16 {%0,%1,%2,%3}, [%4];\n"
                 : "=r"(r0), "=r"(r1), "=r"(r2), "=r"(r3) : "r"(a));
}
__device__ __forceinline__ void ldsm4t(uint32_t& r0, uint32_t& r1,
                                       uint32_t& r2, uint32_t& r3, uint32_t a) {
    asm volatile("ldmatrix.sync.aligned.m8n8.x4.trans.shared.b16 {%0,%1,%2,%3}, [%4];\n"
                 : "=r"(r0), "=r"(r1), "=r"(r2), "=r"(r3) : "r"(a));
}
#define HMMA(accv, a0, a1, a2, a3, b0, b1) \
    asm volatile( \
        "mma.sync.aligned.m16n8k16.row.col.f32.f16.f16.f32 " \
        "{%0,%1,%2,%3}, {%4,%5,%6,%7}, {%8,%9}, {%0,%1,%2,%3};\n" \
        : "+f"((accv)[0]), "+f"((accv)[1]), "+f"((accv)[2]), "+f"((accv)[3]) \
        : "r"(a0), "r"(a1), "r"(a2), "r"(a3), "r"(b0), "r"(b1))

// ---------------- rel-pos bias precompute (Morton decode once) --------------
__global__ __launch_bounds__(256) void bias_kernel(
    const float* __restrict__ table, float* __restrict__ out)
{
    int idx = blockIdx.x * 256 + threadIdx.x;   // h*4096 + i*64 + j
    if (idx >= HEADS * 4096) return;
    int h  = idx >> 12;
    int ij = idx & 4095;
    int i  = ij >> 6, j = ij & 63;
    int ri = ((i >> 1) & 1) | (((i >> 3) & 1) << 1) | (((i >> 5) & 1) << 2);
    int ci = (i & 1)        | (((i >> 2) & 1) << 1) | (((i >> 4) & 1) << 2);
    int rj = ((j >> 1) & 1) | (((j >> 3) & 1) << 1) | (((j >> 5) & 1) << 2);
    int cj = (j & 1)        | (((j >> 2) & 1) << 1) | (((j >> 4) & 1) << 2);
    int rpi = (ri - rj + 7) * 15 + (ci - cj + 7);
    out[idx] = table[rpi * HEADS + h];
}

// ---------------- fused weight fp16 pre-convert (single launch) -------------
__global__ __launch_bounds__(256) void cvt_all_kernel(
    const float4* __restrict__ qkvw, const float4* __restrict__ pw,
    const float4* __restrict__ f1w,  const float4* __restrict__ f2w,
    __half* __restrict__ out)
{
    int i = blockIdx.x * 256 + threadIdx.x;            // float4 index over W_TOT
    const int nQ  = 3 * DIMC * DIMC / 4;
    const int nP  = DIMC * DIMC / 4;
    const int nF  = 4 * DIMC * DIMC / 4;
    const float4* src;
    int base = i;
    if (i < nQ)                    { src = qkvw; }
    else if ((base -= nQ) < nP)    { src = pw;  }
    else if ((base -= nP) < nF)    { src = f1w; }
    else if ((base -= nF) < nF)    { src = f2w; }
    else return;
    float4 v = src[base];
    *(__half2*)(out + 4 * i)     = __floats2half2_rn(v.x, v.y);
    *(__half2*)(out + 4 * i + 2) = __floats2half2_rn(v.z, v.w);
}

// ---------------- fused LayerNorm (+ roll), fp16 output --------------------
// 192 threads, one float4 per thread (768 = 192*4), 6-warp reduction.
__global__ __launch_bounds__(192) void ln_kernel(
    const float* __restrict__ x, const float* __restrict__ g,
    const float* __restrict__ b, __half* __restrict__ out, int rollOff)
{
    int r  = blockIdx.x;
    int bb = r / N_TOK;
    int n  = r - bb * N_TOK;
    int src = bb * N_TOK + (n + rollOff) % N_TOK;

    int c = threadIdx.x;                       // 0..191
    float4 v = ((const float4*)(x + (size_t)src * DIMC))[c];
    float s  = v.x + v.y + v.z + v.w;
    float ss = v.x * v.x + v.y * v.y + v.z * v.z + v.w * v.w;
    #pragma unroll
    for (int o = 16; o > 0; o >>= 1) {
        s  += __shfl_xor_sync(0xFFFFFFFFu, s, o);
        ss += __shfl_xor_sync(0xFFFFFFFFu, ss, o);
    }
    __shared__ float sm[6], sm2[6], stat[2];
    int warp = c >> 5;
    if ((c & 31) == 0) { sm[warp] = s; sm2[warp] = ss; }
    __syncthreads();
    if (c == 0) {
        float ts = 0.f, tss = 0.f;
        #pragma unroll
        for (int i = 0; i < 6; i++) { ts += sm[i]; tss += sm2[i]; }
        float m   = ts * (1.f / 768.f);
        float var = tss * (1.f / 768.f) - m * m;
        stat[0] = m;
        stat[1] = rsqrtf(var + 1e-5f);
    }
    __syncthreads();
    float m = stat[0], inv = stat[1];
    float4 gg = ((const float4*)g)[c];
    float4 bv = ((const float4*)b)[c];
    __half2 h0 = __floats2half2_rn((v.x - m) * inv * gg.x + bv.x,
                                   (v.y - m) * inv * gg.y + bv.y);
    __half2 h1 = __floats2half2_rn((v.z - m) * inv * gg.z + bv.z,
                                   (v.w - m) * inv * gg.w + bv.w);
    __half2* orow = (__half2*)(out + (size_t)r * DIMC);
    orow[2 * c]     = h0;
    orow[2 * c + 1] = h1;
}

// =============== fp16 mma.sync GEMM ========================================
// 128x128x64 CTA tile, 128 thr (4 warps 2m x 2n), warp tile 64x64.
// SMEM: 128B rows (64 halfs), 16B chunk swizzle: phys = chunk ^ (row&7).
#define KT 64
#define STAGE_BYTES 32768     // A 16KB + B 16KB
#define NSTAGE 3
#define SMEM_GEMM (NSTAGE * STAGE_BYTES)

template <int EPI>
__global__ __launch_bounds__(128, 2) void hgemm(
    const __half* __restrict__ A, const __half* __restrict__ B,
    const float* __restrict__ bias, const float* __restrict__ res,
    void* __restrict__ Cv, int M, int Nn, int K)
{
    extern __shared__ float smem[];
    uint32_t sbase = (uint32_t)__cvta_generic_to_shared(smem);

    const int tid  = threadIdx.x;
    const int lane = tid & 31;
    const int wid  = tid >> 5;
    const int wm   = wid >> 1;           // 0..1 (m)
    const int wn   = wid & 1;            // 0..1 (n)
    const int g    = lane >> 2;
    const int q    = lane & 3;

    const int rowA0 = blockIdx.y * 128;
    const int rowB0 = blockIdx.x * 128;

    const int ldr = tid >> 3;            // 0..15
    const int lc  = tid & 7;
    const uint32_t pcoff  = (uint32_t)((lc ^ (ldr & 7)) << 4);
    const uint32_t rowOff = (uint32_t)(ldr << 7);
    const __half* gA = A + (size_t)(rowA0 + ldr) * K + lc * 8;
    const __half* gB = B + (size_t)(rowB0 + ldr) * K + lc * 8;

    const int t8  = lane >> 3;
    const int thA = t8 >> 1;
    const int tlA = t8 & 1;
    uint32_t aBaseOff[4]; int aRx[4];
    #pragma unroll
    for (int mf = 0; mf < 4; mf++) {
        int r = wm * 64 + mf * 16 + tlA * 8 + (lane & 7);
        aBaseOff[mf] = (uint32_t)(r << 7);
        aRx[mf] = r & 7;
    }
    const int tbB = t8 & 1;
    uint32_t bBaseOff[4]; int bRx[4];
    #pragma unroll
    for (int p = 0; p < 4; p++) {
        int n = wn * 64 + p * 16 + (t8 >> 1) * 8 + (lane & 7);
        bBaseOff[p] = (uint32_t)(n << 7);
        bRx[p] = n & 7;
    }

    float acc[4][8][4];
    #pragma unroll
    for (int a = 0; a < 4; a++)
        #pragma unroll
        for (int b = 0; b < 8; b++)
            #pragma unroll
            for (int e = 0; e < 4; e++) acc[a][b][e] = 0.f;

    const int nk = K / KT;

    auto issue = [&](int stage, int kt) {
        uint32_t sa = sbase + stage * STAGE_BYTES + rowOff + pcoff;
        uint32_t sb = sa + 16384u;
        const __half* pa = gA + kt * KT;
        const __half* pb = gB + kt * KT;
        #pragma unroll
        for (int r = 0; r < 8; r++) {
            cp16(sa + r * (16u << 7), pa + (size_t)r * 16 * K);
            cp16(sb + r * (16u << 7), pb + (size_t)r * 16 * K);
        }
        asm volatile("cp.async.commit_group;\n");
    };

    issue(0, 0);
    issue(1, 1);

    for (int kt = 0; kt < nk; kt++) {
        asm volatile("cp.async.wait_group 1;\n");
        __syncthreads();
        if (kt + 2 < nk) issue((kt + 2) % NSTAGE, kt + 2);
        else asm volatile("cp.async.commit_group;\n");

        uint32_t aS = sbase + (kt % NSTAGE) * STAGE_BYTES;
        uint32_t bS = aS + 16384u;

        #pragma unroll
        for (int j = 0; j < 4; j++) {
            uint32_t af[4][4];
            #pragma unroll
            for (int mf = 0; mf < 4; mf++)
                ldsm4(af[mf][0], af[mf][1], af[mf][2], af[mf][3],
                      aS + aBaseOff[mf] + (uint32_t)(((2 * j + thA) ^ aRx[mf]) << 4));
            uint32_t bf[4][4];
            #pragma unroll
            for (int p = 0; p < 4; p++)
                ldsm4(bf[p][0], bf[p][1], bf[p][2], bf[p][3],
                      bS + bBaseOff[p] + (uint32_t)(((2 * j + tbB) ^ bRx[p]) << 4));
            #pragma unroll
            for (int nf = 0; nf < 8; nf++) {
                uint32_t b0 = bf[nf >> 1][(nf & 1) * 2];
                uint32_t b1 = bf[nf >> 1][(nf & 1) * 2 + 1];
                #pragma unroll
                for (int mf = 0; mf < 4; mf++)
                    HMMA(acc[mf][nf], af[mf][0], af[mf][1], af[mf][2], af[mf][3], b0, b1);
            }
        }
        // no trailing sync: next iteration's top barrier protects stage reuse
    }

    // ---------------- epilogue ----------------
    const int r_base = blockIdx.y * 128 + wm * 64;
    const int c_base = blockIdx.x * 128 + wn * 64;
    #pragma unroll
    for (int mf = 0; mf < 4; mf++) {
        #pragma unroll
        for (int rr = 0; rr < 2; rr++) {
            int r = r_base + mf * 16 + g + rr * 8;
            int outr = r;
            if (EPI == 3) {
                int bb = r / N_TOK;
                int n  = r - bb * N_TOK;
                outr = bb * N_TOK + (n + SHIFT) % N_TOK;
            }
            const float* rrow = (EPI >= 2) ? (res + (size_t)outr * Nn) : (const float*)0;
            #pragma unroll
            for (int nf = 0; nf < 8; nf++) {
                int c = c_base + nf * 8 + q * 2;
                float2 bv = *(const float2*)&bias[c];
                float v0 = acc[mf][nf][rr * 2 + 0] + bv.x;
                float v1 = acc[mf][nf][rr * 2 + 1] + bv.y;
                if (EPI == 1) {
                    v0 = 0.5f * v0 * (1.f + erff(v0 * 0.70710678118f));
                    v1 = 0.5f * v1 * (1.f + erff(v1 * 0.70710678118f));
                }
                if (EPI >= 2) {
                    float2 rv = *(const float2*)&rrow[c];
                    v0 += rv.x; v1 += rv.y;
                    float* crow = (float*)Cv + (size_t)outr * Nn;
                    *(float2*)&crow[c] = make_float2(v0, v1);
                } else {
                    __half* crow = (__half*)Cv + (size_t)outr * Nn;
                    *(__half2*)&crow[c] = __floats2half2_rn(v0, v1);
                }
            }
        }
    }
}

// ---------------- tensor-core windowed attention ---------------------------
// one block per (window, head), 128 threads (4 warps); warp = 16 rows of S/O.
// rel-pos bias pre-expanded to gbias[h][i][j]; mask condition is (nf<4) vs (i<32).
__global__ __launch_bounds__(128) void attn_kernel(
    const __half* __restrict__ qkv, const float* __restrict__ gbias,
    __half* __restrict__ out)
{
    __shared__ __half sQ[64 * 64];
    __shared__ __half sK[64 * 64];
    __shared__ __half sV[64 * 64];

    const int w = blockIdx.x, h = blockIdx.y;
    const int tid = threadIdx.x;
    const int lane = tid & 31;
    const int wid = tid >> 5;
    const int g = lane >> 2, q = lane & 3;
    const int t8 = lane >> 3;

    const uint32_t bQ = (uint32_t)__cvta_generic_to_shared(sQ);
    const uint32_t bK = (uint32_t)__cvta_generic_to_shared(sK);
    const uint32_t bV = (uint32_t)__cvta_generic_to_shared(sV);

    // ---- load Q/K/V into swizzled smem (128B rows, chunk ^= row&7) --------
    {
        int row = tid >> 1;
        int cb  = (tid & 1) * 4;
        const __half* src = qkv + (size_t)(w * 64 + row) * (3 * DIMC) + h * HD;
        #pragma unroll
        for (int m = 0; m < 3; m++) {
            uint32_t dst = (m == 0 ? bQ : m == 1 ? bK : bV) + (uint32_t)(row << 7);
            const __half* s = src + m * DIMC;
            #pragma unroll
            for (int c = 0; c < 4; c++) {
                int cc = cb + c;
                cp16(dst + (uint32_t)((cc ^ (row & 7)) << 4), s + cc * 8);
            }
        }
        asm volatile("cp.async.commit_group;\n");
        asm volatile("cp.async.wait_group 0;\n");
    }
    __syncthreads();

    // ---- fragment address bases ------------------------------------------
    const int thA = t8 >> 1, tlA = t8 & 1;
    int rA = wid * 16 + tlA * 8 + (lane & 7);
    uint32_t aBase = bQ + (uint32_t)(rA << 7);
    int aRx = rA & 7;
    uint32_t kBase[4]; int kRx[4];
    #pragma unroll
    for (int p = 0; p < 4; p++) {
        int n = p * 16 + (t8 >> 1) * 8 + (lane & 7);
        kBase[p] = bK + (uint32_t)(n << 7);
        kRx[p] = n & 7;
    }
    const int tbB = t8 & 1;

    // ---- S = Q @ K^T (unscaled) ------------------------------------------
    float acc[8][4];
    #pragma unroll
    for (int nf = 0; nf < 8; nf++)
        #pragma unroll
        for (int e = 0; e < 4; e++) acc[nf][e] = 0.f;

    #pragma unroll
    for (int kc = 0; kc < 4; kc++) {
        uint32_t a0, a1, a2, a3;
        ldsm4(a0, a1, a2, a3, aBase + (uint32_t)(((2 * kc + thA) ^ aRx) << 4));
        uint32_t bfr[4][4];
        #pragma unroll
        for (int p = 0; p < 4; p++)
            ldsm4(bfr[p][0], bfr[p][1], bfr[p][2], bfr[p][3],
                  kBase[p] + (uint32_t)(((2 * kc + tbB) ^ kRx[p]) << 4));
        #pragma unroll
        for (int nf = 0; nf < 8; nf++) {
            uint32_t b0 = bfr[nf >> 1][(nf & 1) * 2];
            uint32_t b1 = bfr[nf >> 1][(nf & 1) * 2 + 1];
            HMMA(acc[nf], a0, a1, a2, a3, b0, b1);
        }
    }

    // ---- bias + mask + softmax on fragments ------------------------------
    const int i0 = wid * 16 + g;
    const int i1 = i0 + 8;
    const bool maskw = (w % NWIN) == (NWIN - 1);
    const float2* bb0 = (const float2*)(gbias + (size_t)h * 4096 + i0 * 64);
    const float2* bb1 = (const float2*)(gbias + (size_t)h * 4096 + i1 * 64);
    // mask: subtract 100 where (i<32) != (j<32); (j<32) == (nf<4); i0<32 == i1<32
    const float msk0 = (maskw && (i0 < 32)) ? 0.f : (maskw ? 100.f : 0.f);   // nf<4 penalty for row i0
    const float msk1 = (maskw && (i0 < 32)) ? 100.f : 0.f;                   // nf>=4 penalty

    float mx0 = -1e30f, mx1 = -1e30f;
    #pragma unroll
    for (int nf = 0; nf < 8; nf++) {
        float2 b0 = bb0[nf * 4 + q];
        float2 b1 = bb1[nf * 4 + q];
        float pen = (nf < 4) ? msk0 : msk1;
        acc[nf][0] = acc[nf][0] * SCALE + b0.x - pen;
        acc[nf][1] = acc[nf][1] * SCALE + b0.y - pen;
        acc[nf][2] = acc[nf][2] * SCALE + b1.x - pen;
        acc[nf][3] = acc[nf][3] * SCALE + b1.y - pen;
        mx0 = fmaxf(mx0, fmaxf(acc[nf][0], acc[nf][1]));
        mx1 = fmaxf(mx1, fmaxf(acc[nf][2], acc[nf][3]));
    }
    mx0 = fmaxf(mx0, __shfl_xor_sync(0xFFFFFFFFu, mx0, 1));
    mx0 = fmaxf(mx0, __shfl_xor_sync(0xFFFFFFFFu, mx0, 2));
    mx1 = fmaxf(mx1, __shfl_xor_sync(0xFFFFFFFFu, mx1, 1));
    mx1 = fmaxf(mx1, __shfl_xor_sync(0xFFFFFFFFu, mx1, 2));
    float sum0 = 0.f, sum1 = 0.f;
    #pragma unroll
    for (int nf = 0; nf < 8; nf++) {
        acc[nf][0] = __expf(acc[nf][0] - mx0); sum0 += acc[nf][0];
        acc[nf][1] = __expf(acc[nf][1] - mx0); sum0 += acc[nf][1];
        acc[nf][2] = __expf(acc[nf][2] - mx1); sum1 += acc[nf][2];
        acc[nf][3] = __expf(acc[nf][3] - mx1); sum1 += acc[nf][3];
    }
    sum0 += __shfl_xor_sync(0xFFFFFFFFu, sum0, 1);
    sum0 += __shfl_xor_sync(0xFFFFFFFFu, sum0, 2);
    sum1 += __shfl_xor_sync(0xFFFFFFFFu, sum1, 1);
    sum1 += __shfl_xor_sync(0xFFFFFFFFu, sum1, 2);
    float inv0 = 1.f / sum0, inv1 = 1.f / sum1;

    // P fragments (fp16): lo = rows g, hi = rows g+8
    uint32_t plo[8], phi[8];
    #pragma unroll
    for (int nf = 0; nf < 8; nf++) {
        __half2 l = __floats2half2_rn(acc[nf][0] * inv0, acc[nf][1] * inv0);
        __half2 hh = __floats2half2_rn(acc[nf][2] * inv1, acc[nf][3] * inv1);
        plo[nf] = *(uint32_t*)&l;
        phi[nf] = *(uint32_t*)&hh;
    }

    // ---- O = P @ V  (V via ldmatrix.trans); reuse acc as O accumulator ----
    #pragma unroll
    for (int nf = 0; nf < 8; nf++)
        #pragma unroll
        for (int e = 0; e < 4; e++) acc[nf][e] = 0.f;

    const int jOff = (t8 & 1) * 8 + (lane & 7);
    const int vsub = t8 >> 1;
    #pragma unroll
    for (int kc = 0; kc < 4; kc++) {
        int j = kc * 16 + jOff;
        uint32_t vb[4][4];
        #pragma unroll
        for (int p = 0; p < 4; p++) {
            int cc = p * 2 + vsub;
            ldsm4t(vb[p][0], vb[p][1], vb[p][2], vb[p][3],
                   bV + (uint32_t)(j << 7) + (uint32_t)((cc ^ (j & 7)) << 4));
        }
        uint32_t a0 = plo[2 * kc], a1 = phi[2 * kc];
        uint32_t a2 = plo[2 * kc + 1], a3 = phi[2 * kc + 1];
        #pragma unroll
        for (int nf = 0; nf < 8; nf++) {
            uint32_t b0 = vb[nf >> 1][(nf & 1) * 2];
            uint32_t b1 = vb[nf >> 1][(nf & 1) * 2 + 1];
            HMMA(acc[nf], a0, a1, a2, a3, b0, b1);
        }
    }

    // ---- write O ----------------------------------------------------------
    __half* o0 = out + (size_t)(w * 64 + i0) * DIMC + h * HD;
    __half* o1 = out + (size_t)(w * 64 + i1) * DIMC + h * HD;
    #pragma unroll
    for (int nf = 0; nf < 8; nf++) {
        int c = nf * 8 + q * 2;
        *(__half2*)(o0 + c) = __floats2half2_rn(acc[nf][0], acc[nf][1]);
        *(__half2*)(o1 + c) = __floats2half2_rn(acc[nf][2], acc[nf][3]);
    }
}

// ---------------- launch ---------------------------------------------------
extern "C" void kernel_launch(void* const* d_in, const int* in_sizes, int n_in,
                              void* d_out, int out_size)
{
    const float* x    = (const float*)d_in[0];
    const float* n1g  = (const float*)d_in[1];
    const float* n1b  = (const float*)d_in[2];
    const float* qkvw = (const float*)d_in[3];
    const float* qkvb = (const float*)d_in[4];
    const float* tab  = (const float*)d_in[5];
    const float* pw   = (const float*)d_in[6];
    const float* pb   = (const float*)d_in[7];
    const float* n2g  = (const float*)d_in[8];
    const float* n2b  = (const float*)d_in[9];
    const float* f1w  = (const float*)d_in[10];
    const float* f1b  = (const float*)d_in[11];
    const float* f2w  = (const float*)d_in[12];
    const float* f2b  = (const float*)d_in[13];
    float* out = (float*)d_out;

    __half *big, *hs, *oB, *wt;
    float *x2, *gb;
    cudaGetSymbolAddress((void**)&big, g_big);
    cudaGetSymbolAddress((void**)&hs,  g_hs);
    cudaGetSymbolAddress((void**)&oB,  g_o);
    cudaGetSymbolAddress((void**)&x2,  g_x2);
    cudaGetSymbolAddress((void**)&wt,  g_wt);
    cudaGetSymbolAddress((void**)&gb,  g_bias);
    __half* qkvB = big;
    __half* mid  = big;

    static int smem_set = 0;
    if (!smem_set) {
        cudaFuncSetAttribute(hgemm<0>, cudaFuncAttributeMaxDynamicSharedMemorySize, SMEM_GEMM);
        cudaFuncSetAttribute(hgemm<1>, cudaFuncAttributeMaxDynamicSharedMemorySize, SMEM_GEMM);
        cudaFuncSetAttribute(hgemm<2>, cudaFuncAttributeMaxDynamicSharedMemorySize, SMEM_GEMM);
        cudaFuncSetAttribute(hgemm<3>, cudaFuncAttributeMaxDynamicSharedMemorySize, SMEM_GEMM);
        smem_set = 1;
    }

    // precompute rel-pos bias matrix + weight fp16 pre-convert
    bias_kernel<<<(HEADS * 4096 + 255) / 256, 256>>>(tab, gb);
    {
        int n4 = W_TOT / 4;
        cvt_all_kernel<<<(n4 + 255) / 256, 256>>>(
            (const float4*)qkvw, (const float4*)pw,
            (const float4*)f1w,  (const float4*)f2w, wt);
    }

    // 1. LN1 + roll(-32)
    ln_kernel<<<M_ROWS, 192>>>(x, n1g, n1b, hs, SHIFT);
    // 2. QKV projection (24576 x 2304 x 768)
    hgemm<0><<<dim3(2304 / 128, M_ROWS / 128), 128, SMEM_GEMM>>>(
        hs, wt + W_QKV, qkvb, nullptr, qkvB, M_ROWS, 3 * DIMC, DIMC);
    // 3. windowed attention (tensor-core)
    attn_kernel<<<dim3(BATCH * NWIN, HEADS), 128>>>(qkvB, gb, oB);
    // 4. proj + roll(+32) + residual -> x2
    hgemm<3><<<dim3(DIMC / 128, M_ROWS / 128), 128, SMEM_GEMM>>>(
        oB, wt + W_PROJ, pb, x, x2, M_ROWS, DIMC, DIMC);
    // 5. LN2
    ln_kernel<<<M_ROWS, 192>>>(x2, n2g, n2b, hs, 0);
    // 6. fc1 + GELU (24576 x 3072 x 768)
    hgemm<1><<<dim3(3072 / 128, M_ROWS / 128), 128, SMEM_GEMM>>>(
        hs, wt + W_FC1, f1b, nullptr, mid, M_ROWS, 4 * DIMC, DIMC);
    // 7. fc2 + residual -> out (24576 x 768 x 3072)
    hgemm<2><<<dim3(DIMC / 128, M_ROWS / 128), 128, SMEM_GEMM>>>(
        mid, wt + W_FC2, f2b, x2, out, M_ROWS, DIMC, 4 * DIMC);
}

// round 14
// speedup vs baseline: 1.0185x; 1.0185x over previous
#include <cuda_runtime.h>
#include <cuda_fp16.h>
#include <math.h>
#include <stdint.h>

#define N_TOK 12288
#define DIMC  768
#define HEADS 12
#define HD    64
#define NWIN  192
#define BATCH 2
#define M_ROWS (BATCH * N_TOK)   // 24576
#define SHIFT 32
#define SCALE 0.125f

// ---------------- scratch (device globals) ---------------------------------
__device__ __half g_big[M_ROWS * 4 * DIMC];   // qkv scratch, later MLP hidden
__device__ __half g_hs [M_ROWS * DIMC];       // LN outputs (fp16)
__device__ __half g_o  [M_ROWS * DIMC];       // attention out (fp16)
__device__ float  g_x2 [M_ROWS * DIMC];       // x + proj residual (fp32)
__device__ float  g_bias[HEADS * 64 * 64];    // precomputed rel-pos bias
#define W_QKV 0
#define W_PROJ (W_QKV + 3 * DIMC * DIMC)
#define W_FC1  (W_PROJ + DIMC * DIMC)
#define W_FC2  (W_FC1 + 4 * DIMC * DIMC)
#define W_TOT  (W_FC2 + 4 * DIMC * DIMC)
__device__ __half g_wt[W_TOT];

// ---------------- helpers ---------------------------------------------------
__device__ __forceinline__ void cp16(uint32_t dst, const void* src) {
    asm volatile("cp.async.cg.shared.global [%0], [%1], 16;\n" :: "r"(dst), "l"(src));
}
__device__ __forceinline__ void ldsm4(uint32_t& r0, uint32_t& r1,
                                      uint32_t& r2, uint32_t& r3, uint32_t a) {
    asm volatile("ldmatrix.sync.aligned.m8n8.x4.shared.b16 {%0,%1,%2,%3}, [%4];\n"
                 : "=r"(r0), "=r"(r1), "=r"(r2), "=r"(r3) : "r"(a));
}
__device__ __forceinline__ void ldsm4t(uint32_t& r0, uint32_t& r1,
                                       uint32_t& r2, uint32_t& r3, uint32_t a) {
    asm volatile("ldmatrix.sync.aligned.m8n8.x4.trans.shared.b16 {%0,%1,%2,%3}, [%4];\n"
                 : "=r"(r0), "=r"(r1), "=r"(r2), "=r"(r3) : "r"(a));
}
#define HMMA(accv, a0, a1, a2, a3, b0, b1) \
    asm volatile( \
        "mma.sync.aligned.m16n8k16.row.col.f32.f16.f16.f32 " \
        "{%0,%1,%2,%3}, {%4,%5,%6,%7}, {%8,%9}, {%0,%1,%2,%3};\n" \
        : "+f"((accv)[0]), "+f"((accv)[1]), "+f"((accv)[2]), "+f"((accv)[3]) \
        : "r"(a0), "r"(a1), "r"(a2), "r"(a3), "r"(b0), "r"(b1))

// ---------------- rel-pos bias precompute (Morton decode once) --------------
__global__ __launch_bounds__(256) void bias_kernel(
    const float* __restrict__ table, float* __restrict__ out)
{
    int idx = blockIdx.x * 256 + threadIdx.x;   // h*4096 + i*64 + j
    if (idx >= HEADS * 4096) return;
    int h  = idx >> 12;
    int ij = idx & 4095;
    int i  = ij >> 6, j = ij & 63;
    int ri = ((i >> 1) & 1) | (((i >> 3) & 1) << 1) | (((i >> 5) & 1) << 2);
    int ci = (i & 1)        | (((i >> 2) & 1) << 1) | (((i >> 4) & 1) << 2);
    int rj = ((j >> 1) & 1) | (((j >> 3) & 1) << 1) | (((j >> 5) & 1) << 2);
    int cj = (j & 1)        | (((j >> 2) & 1) << 1) | (((j >> 4) & 1) << 2);
    int rpi = (ri - rj + 7) * 15 + (ci - cj + 7);
    out[idx] = table[rpi * HEADS + h];
}

// ---------------- fused weight fp16 pre-convert (single launch) -------------
__global__ __launch_bounds__(256) void cvt_all_kernel(
    const float4* __restrict__ qkvw, const float4* __restrict__ pw,
    const float4* __restrict__ f1w,  const float4* __restrict__ f2w,
    __half* __restrict__ out)
{
    int i = blockIdx.x * 256 + threadIdx.x;            // float4 index over W_TOT
    const int nQ  = 3 * DIMC * DIMC / 4;
    const int nP  = DIMC * DIMC / 4;
    const int nF  = 4 * DIMC * DIMC / 4;
    const float4* src;
    int base = i;
    if (i < nQ)                    { src = qkvw; }
    else if ((base -= nQ) < nP)    { src = pw;  }
    else if ((base -= nP) < nF)    { src = f1w; }
    else if ((base -= nF) < nF)    { src = f2w; }
    else return;
    float4 v = src[base];
    *(__half2*)(out + 4 * i)     = __floats2half2_rn(v.x, v.y);
    *(__half2*)(out + 4 * i + 2) = __floats2half2_rn(v.z, v.w);
}

// ---------------- fused LayerNorm (+ roll), warp-per-row, fp16 output ------
// 256 thr = 8 warps = 8 rows/block; pure shfl reduction, no smem/syncthreads.
__global__ __launch_bounds__(256) void ln_kernel(
    const float* __restrict__ x, const float* __restrict__ g,
    const float* __restrict__ b, __half* __restrict__ out, int rollOff)
{
    int warp = threadIdx.x >> 5;
    int lane = threadIdx.x & 31;
    int r  = blockIdx.x * 8 + warp;
    int bb = r / N_TOK;
    int n  = r - bb * N_TOK;
    int src = bb * N_TOK + (n + rollOff) % N_TOK;

    const float4* xr = (const float4*)(x + (size_t)src * DIMC);
    float4 v[6];
    float s = 0.f, ss = 0.f;
    #pragma unroll
    for (int k = 0; k < 6; k++) {
        v[k] = xr[lane + 32 * k];
        s  += v[k].x + v[k].y + v[k].z + v[k].w;
        ss += v[k].x * v[k].x + v[k].y * v[k].y + v[k].z * v[k].z + v[k].w * v[k].w;
    }
    #pragma unroll
    for (int o = 16; o > 0; o >>= 1) {
        s  += __shfl_xor_sync(0xFFFFFFFFu, s, o);
        ss += __shfl_xor_sync(0xFFFFFFFFu, ss, o);
    }
    float m   = s * (1.f / 768.f);
    float inv = rsqrtf(ss * (1.f / 768.f) - m * m + 1e-5f);

    const float4* g4 = (const float4*)g;
    const float4* b4 = (const float4*)b;
    __half2* orow = (__half2*)(out + (size_t)r * DIMC);
    #pragma unroll
    for (int k = 0; k < 6; k++) {
        float4 gg = g4[lane + 32 * k];
        float4 bv = b4[lane + 32 * k];
        orow[2 * (lane + 32 * k)]     = __floats2half2_rn(
            (v[k].x - m) * inv * gg.x + bv.x, (v[k].y - m) * inv * gg.y + bv.y);
        orow[2 * (lane + 32 * k) + 1] = __floats2half2_rn(
            (v[k].z - m) * inv * gg.z + bv.z, (v[k].w - m) * inv * gg.w + bv.w);
    }
}

// =============== fp16 mma.sync GEMM ========================================
// 128x128x64 CTA tile, 128 thr (4 warps 2m x 2n), warp tile 64x64.
// SMEM: 128B rows (64 halfs), 16B chunk swizzle: phys = chunk ^ (row&7).
#define KT 64
#define STAGE_BYTES 32768     // A 16KB + B 16KB
#define NSTAGE 3
#define SMEM_GEMM (NSTAGE * STAGE_BYTES)

template <int EPI>
__global__ __launch_bounds__(128, 2) void hgemm(
    const __half* __restrict__ A, const __half* __restrict__ B,
    const float* __restrict__ bias, const float* __restrict__ res,
    void* __restrict__ Cv, int M, int Nn, int K)
{
    extern __shared__ float smem[];
    uint32_t sbase = (uint32_t)__cvta_generic_to_shared(smem);

    const int tid  = threadIdx.x;
    const int lane = tid & 31;
    const int wid  = tid >> 5;
    const int wm   = wid >> 1;           // 0..1 (m)
    const int wn   = wid & 1;            // 0..1 (n)
    const int g    = lane >> 2;
    const int q    = lane & 3;

    const int rowA0 = blockIdx.y * 128;
    const int rowB0 = blockIdx.x * 128;

    const int ldr = tid >> 3;            // 0..15
    const int lc  = tid & 7;
    const uint32_t pcoff  = (uint32_t)((lc ^ (ldr & 7)) << 4);
    const uint32_t rowOff = (uint32_t)(ldr << 7);
    const __half* gA = A + (size_t)(rowA0 + ldr) * K + lc * 8;
    const __half* gB = B + (size_t)(rowB0 + ldr) * K + lc * 8;

    const int t8  = lane >> 3;
    const int thA = t8 >> 1;
    const int tlA = t8 & 1;
    uint32_t aBaseOff[4]; int aRx[4];
    #pragma unroll
    for (int mf = 0; mf < 4; mf++) {
        int r = wm * 64 + mf * 16 + tlA * 8 + (lane & 7);
        aBaseOff[mf] = (uint32_t)(r << 7);
        aRx[mf] = r & 7;
    }
    const int tbB = t8 & 1;
    uint32_t bBaseOff[4]; int bRx[4];
    #pragma unroll
    for (int p = 0; p < 4; p++) {
        int n = wn * 64 + p * 16 + (t8 >> 1) * 8 + (lane & 7);
        bBaseOff[p] = (uint32_t)(n << 7);
        bRx[p] = n & 7;
    }

    float acc[4][8][4];
    #pragma unroll
    for (int a = 0; a < 4; a++)
        #pragma unroll
        for (int b = 0; b < 8; b++)
            #pragma unroll
            for (int e = 0; e < 4; e++) acc[a][b][e] = 0.f;

    const int nk = K / KT;

    auto issue = [&](int stage, int kt) {
        uint32_t sa = sbase + stage * STAGE_BYTES + rowOff + pcoff;
        uint32_t sb = sa + 16384u;
        const __half* pa = gA + kt * KT;
        const __half* pb = gB + kt * KT;
        #pragma unroll
        for (int r = 0; r < 8; r++) {
            cp16(sa + r * (16u << 7), pa + (size_t)r * 16 * K);
            cp16(sb + r * (16u << 7), pb + (size_t)r * 16 * K);
        }
        asm volatile("cp.async.commit_group;\n");
    };

    issue(0, 0);
    issue(1, 1);

    for (int kt = 0; kt < nk; kt++) {
        asm volatile("cp.async.wait_group 1;\n");
        __syncthreads();
        if (kt + 2 < nk) issue((kt + 2) % NSTAGE, kt + 2);
        else asm volatile("cp.async.commit_group;\n");

        uint32_t aS = sbase + (kt % NSTAGE) * STAGE_BYTES;
        uint32_t bS = aS + 16384u;

        #pragma unroll
        for (int j = 0; j < 4; j++) {
            uint32_t af[4][4];
            #pragma unroll
            for (int mf = 0; mf < 4; mf++)
                ldsm4(af[mf][0], af[mf][1], af[mf][2], af[mf][3],
                      aS + aBaseOff[mf] + (uint32_t)(((2 * j + thA) ^ aRx[mf]) << 4));
            uint32_t bf[4][4];
            #pragma unroll
            for (int p = 0; p < 4; p++)
                ldsm4(bf[p][0], bf[p][1], bf[p][2], bf[p][3],
                      bS + bBaseOff[p] + (uint32_t)(((2 * j + tbB) ^ bRx[p]) << 4));
            #pragma unroll
            for (int nf = 0; nf < 8; nf++) {
                uint32_t b0 = bf[nf >> 1][(nf & 1) * 2];
                uint32_t b1 = bf[nf >> 1][(nf & 1) * 2 + 1];
                #pragma unroll
                for (int mf = 0; mf < 4; mf++)
                    HMMA(acc[mf][nf], af[mf][0], af[mf][1], af[mf][2], af[mf][3], b0, b1);
            }
        }
        // no trailing sync: next iteration's top barrier protects stage reuse
    }

    // ---------------- epilogue ----------------
    const int r_base = blockIdx.y * 128 + wm * 64;
    const int c_base = blockIdx.x * 128 + wn * 64;
    #pragma unroll
    for (int mf = 0; mf < 4; mf++) {
        #pragma unroll
        for (int rr = 0; rr < 2; rr++) {
            int r = r_base + mf * 16 + g + rr * 8;
            int outr = r;
            if (EPI == 3) {
                int bb = r / N_TOK;
                int n  = r - bb * N_TOK;
                outr = bb * N_TOK + (n + SHIFT) % N_TOK;
            }
            const float* rrow = (EPI >= 2) ? (res + (size_t)outr * Nn) : (const float*)0;
            #pragma unroll
            for (int nf = 0; nf < 8; nf++) {
                int c = c_base + nf * 8 + q * 2;
                float2 bv = *(const float2*)&bias[c];
                float v0 = acc[mf][nf][rr * 2 + 0] + bv.x;
                float v1 = acc[mf][nf][rr * 2 + 1] + bv.y;
                if (EPI == 1) {
                    v0 = 0.5f * v0 * (1.f + erff(v0 * 0.70710678118f));
                    v1 = 0.5f * v1 * (1.f + erff(v1 * 0.70710678118f));
                }
                if (EPI >= 2) {
                    float2 rv = *(const float2*)&rrow[c];
                    v0 += rv.x; v1 += rv.y;
                    float* crow = (float*)Cv + (size_t)outr * Nn;
                    *(float2*)&crow[c] = make_float2(v0, v1);
                } else {
                    __half* crow = (__half*)Cv + (size_t)outr * Nn;
                    *(__half2*)&crow[c] = __floats2half2_rn(v0, v1);
                }
            }
        }
    }
}

// ---------------- tensor-core windowed attention ---------------------------
// one block per (window, head), 128 threads (4 warps); warp = 16 rows of S/O.
// launch_bounds(128,8): cap regs at 64 -> 8 CTAs/SM for latency hiding.
__global__ __launch_bounds__(128, 8) void attn_kernel(
    const __half* __restrict__ qkv, const float* __restrict__ gbias,
    __half* __restrict__ out)
{
    __shared__ __half sQ[64 * 64];
    __shared__ __half sK[64 * 64];
    __shared__ __half sV[64 * 64];

    const int w = blockIdx.x, h = blockIdx.y;
    const int tid = threadIdx.x;
    const int lane = tid & 31;
    const int wid = tid >> 5;
    const int g = lane >> 2, q = lane & 3;
    const int t8 = lane >> 3;

    const uint32_t bQ = (uint32_t)__cvta_generic_to_shared(sQ);
    const uint32_t bK = (uint32_t)__cvta_generic_to_shared(sK);
    const uint32_t bV = (uint32_t)__cvta_generic_to_shared(sV);

    // ---- load Q/K/V into swizzled smem (128B rows, chunk ^= row&7) --------
    {
        int row = tid >> 1;
        int cb  = (tid & 1) * 4;
        const __half* src = qkv + (size_t)(w * 64 + row) * (3 * DIMC) + h * HD;
        #pragma unroll
        for (int m = 0; m < 3; m++) {
            uint32_t dst = (m == 0 ? bQ : m == 1 ? bK : bV) + (uint32_t)(row << 7);
            const __half* s = src + m * DIMC;
            #pragma unroll
            for (int c = 0; c < 4; c++) {
                int cc = cb + c;
                cp16(dst + (uint32_t)((cc ^ (row & 7)) << 4), s + cc * 8);
            }
        }
        asm volatile("cp.async.commit_group;\n");
        asm volatile("cp.async.wait_group 0;\n");
    }
    __syncthreads();

    // ---- fragment address bases ------------------------------------------
    const int thA = t8 >> 1, tlA = t8 & 1;
    int rA = wid * 16 + tlA * 8 + (lane & 7);
    uint32_t aBase = bQ + (uint32_t)(rA << 7);
    int aRx = rA & 7;
    uint32_t kBase[4]; int kRx[4];
    #pragma unroll
    for (int p = 0; p < 4; p++) {
        int n = p * 16 + (t8 >> 1) * 8 + (lane & 7);
        kBase[p] = bK + (uint32_t)(n << 7);
        kRx[p] = n & 7;
    }
    const int tbB = t8 & 1;

    // ---- S = Q @ K^T (unscaled) ------------------------------------------
    float acc[8][4];
    #pragma unroll
    for (int nf = 0; nf < 8; nf++)
        #pragma unroll
        for (int e = 0; e < 4; e++) acc[nf][e] = 0.f;

    #pragma unroll
    for (int kc = 0; kc < 4; kc++) {
        uint32_t a0, a1, a2, a3;
        ldsm4(a0, a1, a2, a3, aBase + (uint32_t)(((2 * kc + thA) ^ aRx) << 4));
        uint32_t bfr[4][4];
        #pragma unroll
        for (int p = 0; p < 4; p++)
            ldsm4(bfr[p][0], bfr[p][1], bfr[p][2], bfr[p][3],
                  kBase[p] + (uint32_t)(((2 * kc + tbB) ^ kRx[p]) << 4));
        #pragma unroll
        for (int nf = 0; nf < 8; nf++) {
            uint32_t b0 = bfr[nf >> 1][(nf & 1) * 2];
            uint32_t b1 = bfr[nf >> 1][(nf & 1) * 2 + 1];
            HMMA(acc[nf], a0, a1, a2, a3, b0, b1);
        }
    }

    // ---- bias + mask + softmax on fragments ------------------------------
    const int i0 = wid * 16 + g;
    const int i1 = i0 + 8;
    const bool maskw = (w % NWIN) == (NWIN - 1);
    const float2* bb0 = (const float2*)(gbias + (size_t)h * 4096 + i0 * 64);
    const float2* bb1 = (const float2*)(gbias + (size_t)h * 4096 + i1 * 64);
    // mask: subtract 100 where (i<32) != (j<32); (j<32) == (nf<4)
    const float msk0 = (maskw && (i0 < 32)) ? 0.f : (maskw ? 100.f : 0.f);
    const float msk1 = (maskw && (i0 < 32)) ? 100.f : 0.f;

    float mx0 = -1e30f, mx1 = -1e30f;
    #pragma unroll
    for (int nf = 0; nf < 8; nf++) {
        float2 b0 = bb0[nf * 4 + q];
        float2 b1 = bb1[nf * 4 + q];
        float pen = (nf < 4) ? msk0 : msk1;
        acc[nf][0] = acc[nf][0] * SCALE + b0.x - pen;
        acc[nf][1] = acc[nf][1] * SCALE + b0.y - pen;
        acc[nf][2] = acc[nf][2] * SCALE + b1.x - pen;
        acc[nf][3] = acc[nf][3] * SCALE + b1.y - pen;
        mx0 = fmaxf(mx0, fmaxf(acc[nf][0], acc[nf][1]));
        mx1 = fmaxf(mx1, fmaxf(acc[nf][2], acc[nf][3]));
    }
    mx0 = fmaxf(mx0, __shfl_xor_sync(0xFFFFFFFFu, mx0, 1));
    mx0 = fmaxf(mx0, __shfl_xor_sync(0xFFFFFFFFu, mx0, 2));
    mx1 = fmaxf(mx1, __shfl_xor_sync(0xFFFFFFFFu, mx1, 1));
    mx1 = fmaxf(mx1, __shfl_xor_sync(0xFFFFFFFFu, mx1, 2));
    float sum0 = 0.f, sum1 = 0.f;
    #pragma unroll
    for (int nf = 0; nf < 8; nf++) {
        acc[nf][0] = __expf(acc[nf][0] - mx0); sum0 += acc[nf][0];
        acc[nf][1] = __expf(acc[nf][1] - mx0); sum0 += acc[nf][1];
        acc[nf][2] = __expf(acc[nf][2] - mx1); sum1 += acc[nf][2];
        acc[nf][3] = __expf(acc[nf][3] - mx1); sum1 += acc[nf][3];
    }
    sum0 += __shfl_xor_sync(0xFFFFFFFFu, sum0, 1);
    sum0 += __shfl_xor_sync(0xFFFFFFFFu, sum0, 2);
    sum1 += __shfl_xor_sync(0xFFFFFFFFu, sum1, 1);
    sum1 += __shfl_xor_sync(0xFFFFFFFFu, sum1, 2);
    float inv0 = 1.f / sum0, inv1 = 1.f / sum1;

    // P fragments (fp16): lo = rows g, hi = rows g+8
    uint32_t plo[8], phi[8];
    #pragma unroll
    for (int nf = 0; nf < 8; nf++) {
        __half2 l = __floats2half2_rn(acc[nf][0] * inv0, acc[nf][1] * inv0);
        __half2 hh = __floats2half2_rn(acc[nf][2] * inv1, acc[nf][3] * inv1);
        plo[nf] = *(uint32_t*)&l;
        phi[nf] = *(uint32_t*)&hh;
    }

    // ---- O = P @ V  (V via ldmatrix.trans); reuse acc as O accumulator ----
    #pragma unroll
    for (int nf = 0; nf < 8; nf++)
        #pragma unroll
        for (int e = 0; e < 4; e++) acc[nf][e] = 0.f;

    const int jOff = (t8 & 1) * 8 + (lane & 7);
    const int vsub = t8 >> 1;
    #pragma unroll
    for (int kc = 0; kc < 4; kc++) {
        int j = kc * 16 + jOff;
        uint32_t vb[4][4];
        #pragma unroll
        for (int p = 0; p < 4; p++) {
            int cc = p * 2 + vsub;
            ldsm4t(vb[p][0], vb[p][1], vb[p][2], vb[p][3],
                   bV + (uint32_t)(j << 7) + (uint32_t)((cc ^ (j & 7)) << 4));
        }
        uint32_t a0 = plo[2 * kc], a1 = phi[2 * kc];
        uint32_t a2 = plo[2 * kc + 1], a3 = phi[2 * kc + 1];
        #pragma unroll
        for (int nf = 0; nf < 8; nf++) {
            uint32_t b0 = vb[nf >> 1][(nf & 1) * 2];
            uint32_t b1 = vb[nf >> 1][(nf & 1) * 2 + 1];
            HMMA(acc[nf], a0, a1, a2, a3, b0, b1);
        }
    }

    // ---- write O ----------------------------------------------------------
    __half* o0 = out + (size_t)(w * 64 + i0) * DIMC + h * HD;
    __half* o1 = out + (size_t)(w * 64 + i1) * DIMC + h * HD;
    #pragma unroll
    for (int nf = 0; nf < 8; nf++) {
        int c = nf * 8 + q * 2;
        *(__half2*)(o0 + c) = __floats2half2_rn(acc[nf][0], acc[nf][1]);
        *(__half2*)(o1 + c) = __floats2half2_rn(acc[nf][2], acc[nf][3]);
    }
}

// ---------------- launch ---------------------------------------------------
extern "C" void kernel_launch(void* const* d_in, const int* in_sizes, int n_in,
                              void* d_out, int out_size)
{
    const float* x    = (const float*)d_in[0];
    const float* n1g  = (const float*)d_in[1];
    const float* n1b  = (const float*)d_in[2];
    const float* qkvw = (const float*)d_in[3];
    const float* qkvb = (const float*)d_in[4];
    const float* tab  = (const float*)d_in[5];
    const float* pw   = (const float*)d_in[6];
    const float* pb   = (const float*)d_in[7];
    const float* n2g  = (const float*)d_in[8];
    const float* n2b  = (const float*)d_in[9];
    const float* f1w  = (const float*)d_in[10];
    const float* f1b  = (const float*)d_in[11];
    const float* f2w  = (const float*)d_in[12];
    const float* f2b  = (const float*)d_in[13];
    float* out = (float*)d_out;

    __half *big, *hs, *oB, *wt;
    float *x2, *gb;
    cudaGetSymbolAddress((void**)&big, g_big);
    cudaGetSymbolAddress((void**)&hs,  g_hs);
    cudaGetSymbolAddress((void**)&oB,  g_o);
    cudaGetSymbolAddress((void**)&x2,  g_x2);
    cudaGetSymbolAddress((void**)&wt,  g_wt);
    cudaGetSymbolAddress((void**)&gb,  g_bias);
    __half* qkvB = big;
    __half* mid  = big;

    static int smem_set = 0;
    if (!smem_set) {
        cudaFuncSetAttribute(hgemm<0>, cudaFuncAttributeMaxDynamicSharedMemorySize, SMEM_GEMM);
        cudaFuncSetAttribute(hgemm<1>, cudaFuncAttributeMaxDynamicSharedMemorySize, SMEM_GEMM);
        cudaFuncSetAttribute(hgemm<2>, cudaFuncAttributeMaxDynamicSharedMemorySize, SMEM_GEMM);
        cudaFuncSetAttribute(hgemm<3>, cudaFuncAttributeMaxDynamicSharedMemorySize, SMEM_GEMM);
        smem_set = 1;
    }

    // precompute rel-pos bias matrix + weight fp16 pre-convert
    bias_kernel<<<(HEADS * 4096 + 255) / 256, 256>>>(tab, gb);
    {
        int n4 = W_TOT / 4;
        cvt_all_kernel<<<(n4 + 255) / 256, 256>>>(
            (const float4*)qkvw, (const float4*)pw,
            (const float4*)f1w,  (const float4*)f2w, wt);
    }

    // 1. LN1 + roll(-32)
    ln_kernel<<<M_ROWS / 8, 256>>>(x, n1g, n1b, hs, SHIFT);
    // 2. QKV projection (24576 x 2304 x 768)
    hgemm<0><<<dim3(2304 / 128, M_ROWS / 128), 128, SMEM_GEMM>>>(
        hs, wt + W_QKV, qkvb, nullptr, qkvB, M_ROWS, 3 * DIMC, DIMC);
    // 3. windowed attention (tensor-core)
    attn_kernel<<<dim3(BATCH * NWIN, HEADS), 128>>>(qkvB, gb, oB);
    // 4. proj + roll(+32) + residual -> x2
    hgemm<3><<<dim3(DIMC / 128, M_ROWS / 128), 128, SMEM_GEMM>>>(
        oB, wt + W_PROJ, pb, x, x2, M_ROWS, DIMC, DIMC);
    // 5. LN2
    ln_kernel<<<M_ROWS / 8, 256>>>(x2, n2g, n2b, hs, 0);
    // 6. fc1 + GELU (24576 x 3072 x 768)
    hgemm<1><<<dim3(3072 / 128, M_ROWS / 128), 128, SMEM_GEMM>>>(
        hs, wt + W_FC1, f1b, nullptr, mid, M_ROWS, 4 * DIMC, DIMC);
    // 7. fc2 + residual -> out (24576 x 768 x 3072)
    hgemm<2><<<dim3(DIMC / 128, M_ROWS / 128), 128, SMEM_GEMM>>>(
        mid, wt + W_FC2, f2b, x2, out, M_ROWS, DIMC, 4 * DIMC);
}

// round 15
// speedup vs baseline: 1.0264x; 1.0078x over previous
#include <cuda_runtime.h>
#include <cuda_fp16.h>
#include <math.h>
#include <stdint.h>

#define N_TOK 12288
#define DIMC  768
#define HEADS 12
#define HD    64
#define NWIN  192
#define BATCH 2
#define M_ROWS (BATCH * N_TOK)   // 24576
#define SHIFT 32
#define SCALE 0.125f

// ---------------- scratch (device globals) ---------------------------------
__device__ __half g_big[M_ROWS * 4 * DIMC];   // qkv scratch, later MLP hidden
__device__ __half g_hs [M_ROWS * DIMC];       // LN outputs (fp16)
__device__ __half g_o  [M_ROWS * DIMC];       // attention out (fp16)
__device__ float  g_x2 [M_ROWS * DIMC];       // x + proj residual (fp32)
__device__ float  g_bias[HEADS * 64 * 64];    // precomputed rel-pos bias
#define W_QKV 0
#define W_PROJ (W_QKV + 3 * DIMC * DIMC)
#define W_FC1  (W_PROJ + DIMC * DIMC)
#define W_FC2  (W_FC1 + 4 * DIMC * DIMC)
#define W_TOT  (W_FC2 + 4 * DIMC * DIMC)
__device__ __half g_wt[W_TOT];

// ---------------- helpers ---------------------------------------------------
__device__ __forceinline__ void cp16(uint32_t dst, const void* src) {
    asm volatile("cp.async.cg.shared.global [%0], [%1], 16;\n" :: "r"(dst), "l"(src));
}
__device__ __forceinline__ void ldsm4(uint32_t& r0, uint32_t& r1,
                                      uint32_t& r2, uint32_t& r3, uint32_t a) {
    asm volatile("ldmatrix.sync.aligned.m8n8.x4.shared.b16 {%0,%1,%2,%3}, [%4];\n"
                 : "=r"(r0), "=r"(r1), "=r"(r2), "=r"(r3) : "r"(a));
}
__device__ __forceinline__ void ldsm4t(uint32_t& r0, uint32_t& r1,
                                       uint32_t& r2, uint32_t& r3, uint32_t a) {
    asm volatile("ldmatrix.sync.aligned.m8n8.x4.trans.shared.b16 {%0,%1,%2,%3}, [%4];\n"
                 : "=r"(r0), "=r"(r1), "=r"(r2), "=r"(r3) : "r"(a));
}
#define HMMA(accv, a0, a1, a2, a3, b0, b1) \
    asm volatile( \
        "mma.sync.aligned.m16n8k16.row.col.f32.f16.f16.f32 " \
        "{%0,%1,%2,%3}, {%4,%5,%6,%7}, {%8,%9}, {%0,%1,%2,%3};\n" \
        : "+f"((accv)[0]), "+f"((accv)[1]), "+f"((accv)[2]), "+f"((accv)[3]) \
        : "r"(a0), "r"(a1), "r"(a2), "r"(a3), "r"(b0), "r"(b1))

// ---------------- rel-pos bias precompute (Morton decode once) --------------
__global__ __launch_bounds__(256) void bias_kernel(
    const float* __restrict__ table, float* __restrict__ out)
{
    int idx = blockIdx.x * 256 + threadIdx.x;   // h*4096 + i*64 + j
    if (idx >= HEADS * 4096) return;
    int h  = idx >> 12;
    int ij = idx & 4095;
    int i  = ij >> 6, j = ij & 63;
    int ri = ((i >> 1) & 1) | (((i >> 3) & 1) << 1) | (((i >> 5) & 1) << 2);
    int ci = (i & 1)        | (((i >> 2) & 1) << 1) | (((i >> 4) & 1) << 2);
    int rj = ((j >> 1) & 1) | (((j >> 3) & 1) << 1) | (((j >> 5) & 1) << 2);
    int cj = (j & 1)        | (((j >> 2) & 1) << 1) | (((j >> 4) & 1) << 2);
    int rpi = (ri - rj + 7) * 15 + (ci - cj + 7);
    out[idx] = table[rpi * HEADS + h];
}

// ---------------- fused weight fp16 pre-convert (single launch) -------------
__global__ __launch_bounds__(256) void cvt_all_kernel(
    const float4* __restrict__ qkvw, const float4* __restrict__ pw,
    const float4* __restrict__ f1w,  const float4* __restrict__ f2w,
    __half* __restrict__ out)
{
    int i = blockIdx.x * 256 + threadIdx.x;            // float4 index over W_TOT
    const int nQ  = 3 * DIMC * DIMC / 4;
    const int nP  = DIMC * DIMC / 4;
    const int nF  = 4 * DIMC * DIMC / 4;
    const float4* src;
    int base = i;
    if (i < nQ)                    { src = qkvw; }
    else if ((base -= nQ) < nP)    { src = pw;  }
    else if ((base -= nP) < nF)    { src = f1w; }
    else if ((base -= nF) < nF)    { src = f2w; }
    else return;
    float4 v = src[base];
    *(__half2*)(out + 4 * i)     = __floats2half2_rn(v.x, v.y);
    *(__half2*)(out + 4 * i + 2) = __floats2half2_rn(v.z, v.w);
}

// ---------------- fused LayerNorm (+ roll), warp-per-row, fp16 output ------
// 256 thr = 8 warps = 8 rows/block; pure shfl reduction, no smem/syncthreads.
__global__ __launch_bounds__(256) void ln_kernel(
    const float* __restrict__ x, const float* __restrict__ g,
    const float* __restrict__ b, __half* __restrict__ out, int rollOff)
{
    int warp = threadIdx.x >> 5;
    int lane = threadIdx.x & 31;
    int r  = blockIdx.x * 8 + warp;
    int bb = r / N_TOK;
    int n  = r - bb * N_TOK;
    int src = bb * N_TOK + (n + rollOff) % N_TOK;

    const float4* xr = (const float4*)(x + (size_t)src * DIMC);
    float4 v[6];
    float s = 0.f, ss = 0.f;
    #pragma unroll
    for (int k = 0; k < 6; k++) {
        v[k] = xr[lane + 32 * k];
        s  += v[k].x + v[k].y + v[k].z + v[k].w;
        ss += v[k].x * v[k].x + v[k].y * v[k].y + v[k].z * v[k].z + v[k].w * v[k].w;
    }
    #pragma unroll
    for (int o = 16; o > 0; o >>= 1) {
        s  += __shfl_xor_sync(0xFFFFFFFFu, s, o);
        ss += __shfl_xor_sync(0xFFFFFFFFu, ss, o);
    }
    float m   = s * (1.f / 768.f);
    float inv = rsqrtf(ss * (1.f / 768.f) - m * m + 1e-5f);

    const float4* g4 = (const float4*)g;
    const float4* b4 = (const float4*)b;
    __half2* orow = (__half2*)(out + (size_t)r * DIMC);
    #pragma unroll
    for (int k = 0; k < 6; k++) {
        float4 gg = g4[lane + 32 * k];
        float4 bv = b4[lane + 32 * k];
        orow[2 * (lane + 32 * k)]     = __floats2half2_rn(
            (v[k].x - m) * inv * gg.x + bv.x, (v[k].y - m) * inv * gg.y + bv.y);
        orow[2 * (lane + 32 * k) + 1] = __floats2half2_rn(
            (v[k].z - m) * inv * gg.z + bv.z, (v[k].w - m) * inv * gg.w + bv.w);
    }
}

// =============== fp16 mma.sync GEMM ========================================
// 128x128x64 CTA tile, 128 thr (4 warps 2m x 2n), warp tile 64x64.
// SMEM: 128B rows (64 halfs), 16B chunk swizzle: phys = chunk ^ (row&7).
// Mainloop order: barrier -> ldsm(j=0) -> cp.async issue -> HMMAs, so the
// cp issue burst executes under the first fragment-load shadow.
#define KT 64
#define STAGE_BYTES 32768     // A 16KB + B 16KB
#define NSTAGE 3
#define SMEM_GEMM (NSTAGE * STAGE_BYTES)

template <int EPI>
__global__ __launch_bounds__(128, 2) void hgemm(
    const __half* __restrict__ A, const __half* __restrict__ B,
    const float* __restrict__ bias, const float* __restrict__ res,
    void* __restrict__ Cv, int M, int Nn, int K)
{
    extern __shared__ float smem[];
    uint32_t sbase = (uint32_t)__cvta_generic_to_shared(smem);

    const int tid  = threadIdx.x;
    const int lane = tid & 31;
    const int wid  = tid >> 5;
    const int wm   = wid >> 1;           // 0..1 (m)
    const int wn   = wid & 1;            // 0..1 (n)
    const int g    = lane >> 2;
    const int q    = lane & 3;

    const int rowA0 = blockIdx.y * 128;
    const int rowB0 = blockIdx.x * 128;

    const int ldr = tid >> 3;            // 0..15
    const int lc  = tid & 7;
    const uint32_t pcoff  = (uint32_t)((lc ^ (ldr & 7)) << 4);
    const uint32_t rowOff = (uint32_t)(ldr << 7);
    const __half* gA = A + (size_t)(rowA0 + ldr) * K + lc * 8;
    const __half* gB = B + (size_t)(rowB0 + ldr) * K + lc * 8;

    const int t8  = lane >> 3;
    const int thA = t8 >> 1;
    const int tlA = t8 & 1;
    uint32_t aBaseOff[4]; int aRx[4];
    #pragma unroll
    for (int mf = 0; mf < 4; mf++) {
        int r = wm * 64 + mf * 16 + tlA * 8 + (lane & 7);
        aBaseOff[mf] = (uint32_t)(r << 7);
        aRx[mf] = r & 7;
    }
    const int tbB = t8 & 1;
    uint32_t bBaseOff[4]; int bRx[4];
    #pragma unroll
    for (int p = 0; p < 4; p++) {
        int n = wn * 64 + p * 16 + (t8 >> 1) * 8 + (lane & 7);
        bBaseOff[p] = (uint32_t)(n << 7);
        bRx[p] = n & 7;
    }

    float acc[4][8][4];
    #pragma unroll
    for (int a = 0; a < 4; a++)
        #pragma unroll
        for (int b = 0; b < 8; b++)
            #pragma unroll
            for (int e = 0; e < 4; e++) acc[a][b][e] = 0.f;

    const int nk = K / KT;

    auto issue = [&](int stage, int kt) {
        uint32_t sa = sbase + stage * STAGE_BYTES + rowOff + pcoff;
        uint32_t sb = sa + 16384u;
        const __half* pa = gA + kt * KT;
        const __half* pb = gB + kt * KT;
        #pragma unroll
        for (int r = 0; r < 8; r++) {
            cp16(sa + r * (16u << 7), pa + (size_t)r * 16 * K);
            cp16(sb + r * (16u << 7), pb + (size_t)r * 16 * K);
        }
        asm volatile("cp.async.commit_group;\n");
    };

    issue(0, 0);
    issue(1, 1);

    for (int kt = 0; kt < nk; kt++) {
        asm volatile("cp.async.wait_group 1;\n");
        __syncthreads();

        uint32_t aS = sbase + (kt % NSTAGE) * STAGE_BYTES;
        uint32_t bS = aS + 16384u;

        // start j=0 fragment loads first: cp issue below runs in their shadow
        uint32_t af0[4][4], bf0[4][4];
        #pragma unroll
        for (int mf = 0; mf < 4; mf++)
            ldsm4(af0[mf][0], af0[mf][1], af0[mf][2], af0[mf][3],
                  aS + aBaseOff[mf] + (uint32_t)((thA ^ aRx[mf]) << 4));
        #pragma unroll
        for (int p = 0; p < 4; p++)
            ldsm4(bf0[p][0], bf0[p][1], bf0[p][2], bf0[p][3],
                  bS + bBaseOff[p] + (uint32_t)((tbB ^ bRx[p]) << 4));

        if (kt + 2 < nk) issue((kt + 2) % NSTAGE, kt + 2);
        else asm volatile("cp.async.commit_group;\n");

        // j = 0 HMMAs
        #pragma unroll
        for (int nf = 0; nf < 8; nf++) {
            uint32_t b0 = bf0[nf >> 1][(nf & 1) * 2];
            uint32_t b1 = bf0[nf >> 1][(nf & 1) * 2 + 1];
            #pragma unroll
            for (int mf = 0; mf < 4; mf++)
                HMMA(acc[mf][nf], af0[mf][0], af0[mf][1], af0[mf][2], af0[mf][3], b0, b1);
        }

        // j = 1..3
        #pragma unroll
        for (int j = 1; j < 4; j++) {
            uint32_t af[4][4];
            #pragma unroll
            for (int mf = 0; mf < 4; mf++)
                ldsm4(af[mf][0], af[mf][1], af[mf][2], af[mf][3],
                      aS + aBaseOff[mf] + (uint32_t)(((2 * j + thA) ^ aRx[mf]) << 4));
            uint32_t bf[4][4];
            #pragma unroll
            for (int p = 0; p < 4; p++)
                ldsm4(bf[p][0], bf[p][1], bf[p][2], bf[p][3],
                      bS + bBaseOff[p] + (uint32_t)(((2 * j + tbB) ^ bRx[p]) << 4));
            #pragma unroll
            for (int nf = 0; nf < 8; nf++) {
                uint32_t b0 = bf[nf >> 1][(nf & 1) * 2];
                uint32_t b1 = bf[nf >> 1][(nf & 1) * 2 + 1];
                #pragma unroll
                for (int mf = 0; mf < 4; mf++)
                    HMMA(acc[mf][nf], af[mf][0], af[mf][1], af[mf][2], af[mf][3], b0, b1);
            }
        }
        // no trailing sync: next iteration's top barrier protects stage reuse
    }

    // ---------------- epilogue ----------------
    const int r_base = blockIdx.y * 128 + wm * 64;
    const int c_base = blockIdx.x * 128 + wn * 64;
    #pragma unroll
    for (int mf = 0; mf < 4; mf++) {
        #pragma unroll
        for (int rr = 0; rr < 2; rr++) {
            int r = r_base + mf * 16 + g + rr * 8;
            int outr = r;
            if (EPI == 3) {
                int bb = r / N_TOK;
                int n  = r - bb * N_TOK;
                outr = bb * N_TOK + (n + SHIFT) % N_TOK;
            }
            const float* rrow = (EPI >= 2) ? (res + (size_t)outr * Nn) : (const float*)0;
            #pragma unroll
            for (int nf = 0; nf < 8; nf++) {
                int c = c_base + nf * 8 + q * 2;
                float2 bv = *(const float2*)&bias[c];
                float v0 = acc[mf][nf][rr * 2 + 0] + bv.x;
                float v1 = acc[mf][nf][rr * 2 + 1] + bv.y;
                if (EPI == 1) {
                    v0 = 0.5f * v0 * (1.f + erff(v0 * 0.70710678118f));
                    v1 = 0.5f * v1 * (1.f + erff(v1 * 0.70710678118f));
                }
                if (EPI >= 2) {
                    float2 rv = *(const float2*)&rrow[c];
                    v0 += rv.x; v1 += rv.y;
                    float* crow = (float*)Cv + (size_t)outr * Nn;
                    *(float2*)&crow[c] = make_float2(v0, v1);
                } else {
                    __half* crow = (__half*)Cv + (size_t)outr * Nn;
                    *(__half2*)&crow[c] = __floats2half2_rn(v0, v1);
                }
            }
        }
    }
}

// ---------------- tensor-core windowed attention ---------------------------
// one block per (window, head), 128 threads (4 warps); warp = 16 rows of S/O.
// launch_bounds(128,8): cap regs at 64 -> 8 CTAs/SM for latency hiding.
__global__ __launch_bounds__(128, 8) void attn_kernel(
    const __half* __restrict__ qkv, const float* __restrict__ gbias,
    __half* __restrict__ out)
{
    __shared__ __half sQ[64 * 64];
    __shared__ __half sK[64 * 64];
    __shared__ __half sV[64 * 64];

    const int w = blockIdx.x, h = blockIdx.y;
    const int tid = threadIdx.x;
    const int lane = tid & 31;
    const int wid = tid >> 5;
    const int g = lane >> 2, q = lane & 3;
    const int t8 = lane >> 3;

    const uint32_t bQ = (uint32_t)__cvta_generic_to_shared(sQ);
    const uint32_t bK = (uint32_t)__cvta_generic_to_shared(sK);
    const uint32_t bV = (uint32_t)__cvta_generic_to_shared(sV);

    // ---- load Q/K/V into swizzled smem (128B rows, chunk ^= row&7) --------
    {
        int row = tid >> 1;
        int cb  = (tid & 1) * 4;
        const __half* src = qkv + (size_t)(w * 64 + row) * (3 * DIMC) + h * HD;
        #pragma unroll
        for (int m = 0; m < 3; m++) {
            uint32_t dst = (m == 0 ? bQ : m == 1 ? bK : bV) + (uint32_t)(row << 7);
            const __half* s = src + m * DIMC;
            #pragma unroll
            for (int c = 0; c < 4; c++) {
                int cc = cb + c;
                cp16(dst + (uint32_t)((cc ^ (row & 7)) << 4), s + cc * 8);
            }
        }
        asm volatile("cp.async.commit_group;\n");
        asm volatile("cp.async.wait_group 0;\n");
    }
    __syncthreads();

    // ---- fragment address bases ------------------------------------------
    const int thA = t8 >> 1, tlA = t8 & 1;
    int rA = wid * 16 + tlA * 8 + (lane & 7);
    uint32_t aBase = bQ + (uint32_t)(rA << 7);
    int aRx = rA & 7;
    uint32_t kBase[4]; int kRx[4];
    #pragma unroll
    for (int p = 0; p < 4; p++) {
        int n = p * 16 + (t8 >> 1) * 8 + (lane & 7);
        kBase[p] = bK + (uint32_t)(n << 7);
        kRx[p] = n & 7;
    }
    const int tbB = t8 & 1;

    // ---- S = Q @ K^T (unscaled) ------------------------------------------
    float acc[8][4];
    #pragma unroll
    for (int nf = 0; nf < 8; nf++)
        #pragma unroll
        for (int e = 0; e < 4; e++) acc[nf][e] = 0.f;

    #pragma unroll
    for (int kc = 0; kc < 4; kc++) {
        uint32_t a0, a1, a2, a3;
        ldsm4(a0, a1, a2, a3, aBase + (uint32_t)(((2 * kc + thA) ^ aRx) << 4));
        uint32_t bfr[4][4];
        #pragma unroll
        for (int p = 0; p < 4; p++)
            ldsm4(bfr[p][0], bfr[p][1], bfr[p][2], bfr[p][3],
                  kBase[p] + (uint32_t)(((2 * kc + tbB) ^ kRx[p]) << 4));
        #pragma unroll
        for (int nf = 0; nf < 8; nf++) {
            uint32_t b0 = bfr[nf >> 1][(nf & 1) * 2];
            uint32_t b1 = bfr[nf >> 1][(nf & 1) * 2 + 1];
            HMMA(acc[nf], a0, a1, a2, a3, b0, b1);
        }
    }

    // ---- bias + mask + softmax on fragments ------------------------------
    const int i0 = wid * 16 + g;
    const int i1 = i0 + 8;
    const bool maskw = (w % NWIN) == (NWIN - 1);
    const float2* bb0 = (const float2*)(gbias + (size_t)h * 4096 + i0 * 64);
    const float2* bb1 = (const float2*)(gbias + (size_t)h * 4096 + i1 * 64);
    // mask: subtract 100 where (i<32) != (j<32); (j<32) == (nf<4)
    const float msk0 = (maskw && (i0 < 32)) ? 0.f : (maskw ? 100.f : 0.f);
    const float msk1 = (maskw && (i0 < 32)) ? 100.f : 0.f;

    float mx0 = -1e30f, mx1 = -1e30f;
    #pragma unroll
    for (int nf = 0; nf < 8; nf++) {
        float2 b0 = bb0[nf * 4 + q];
        float2 b1 = bb1[nf * 4 + q];
        float pen = (nf < 4) ? msk0 : msk1;
        acc[nf][0] = acc[nf][0] * SCALE + b0.x - pen;
        acc[nf][1] = acc[nf][1] * SCALE + b0.y - pen;
        acc[nf][2] = acc[nf][2] * SCALE + b1.x - pen;
        acc[nf][3] = acc[nf][3] * SCALE + b1.y - pen;
        mx0 = fmaxf(mx0, fmaxf(acc[nf][0], acc[nf][1]));
        mx1 = fmaxf(mx1, fmaxf(acc[nf][2], acc[nf][3]));
    }
    mx0 = fmaxf(mx0, __shfl_xor_sync(0xFFFFFFFFu, mx0, 1));
    mx0 = fmaxf(mx0, __shfl_xor_sync(0xFFFFFFFFu, mx0, 2));
    mx1 = fmaxf(mx1, __shfl_xor_sync(0xFFFFFFFFu, mx1, 1));
    mx1 = fmaxf(mx1, __shfl_xor_sync(0xFFFFFFFFu, mx1, 2));
    float sum0 = 0.f, sum1 = 0.f;
    #pragma unroll
    for (int nf = 0; nf < 8; nf++) {
        acc[nf][0] = __expf(acc[nf][0] - mx0); sum0 += acc[nf][0];
        acc[nf][1] = __expf(acc[nf][1] - mx0); sum0 += acc[nf][1];
        acc[nf][2] = __expf(acc[nf][2] - mx1); sum1 += acc[nf][2];
        acc[nf][3] = __expf(acc[nf][3] - mx1); sum1 += acc[nf][3];
    }
    sum0 += __shfl_xor_sync(0xFFFFFFFFu, sum0, 1);
    sum0 += __shfl_xor_sync(0xFFFFFFFFu, sum0, 2);
    sum1 += __shfl_xor_sync(0xFFFFFFFFu, sum1, 1);
    sum1 += __shfl_xor_sync(0xFFFFFFFFu, sum1, 2);
    float inv0 = 1.f / sum0, inv1 = 1.f / sum1;

    // P fragments (fp16): lo = rows g, hi = rows g+8
    uint32_t plo[8], phi[8];
    #pragma unroll
    for (int nf = 0; nf < 8; nf++) {
        __half2 l = __floats2half2_rn(acc[nf][0] * inv0, acc[nf][1] * inv0);
        __half2 hh = __floats2half2_rn(acc[nf][2] * inv1, acc[nf][3] * inv1);
        plo[nf] = *(uint32_t*)&l;
        phi[nf] = *(uint32_t*)&hh;
    }

    // ---- O = P @ V  (V via ldmatrix.trans); reuse acc as O accumulator ----
    #pragma unroll
    for (int nf = 0; nf < 8; nf++)
        #pragma unroll
        for (int e = 0; e < 4; e++) acc[nf][e] = 0.f;

    const int jOff = (t8 & 1) * 8 + (lane & 7);
    const int vsub = t8 >> 1;
    #pragma unroll
    for (int kc = 0; kc < 4; kc++) {
        int j = kc * 16 + jOff;
        uint32_t vb[4][4];
        #pragma unroll
        for (int p = 0; p < 4; p++) {
            int cc = p * 2 + vsub;
            ldsm4t(vb[p][0], vb[p][1], vb[p][2], vb[p][3],
                   bV + (uint32_t)(j << 7) + (uint32_t)((cc ^ (j & 7)) << 4));
        }
        uint32_t a0 = plo[2 * kc], a1 = phi[2 * kc];
        uint32_t a2 = plo[2 * kc + 1], a3 = phi[2 * kc + 1];
        #pragma unroll
        for (int nf = 0; nf < 8; nf++) {
            uint32_t b0 = vb[nf >> 1][(nf & 1) * 2];
            uint32_t b1 = vb[nf >> 1][(nf & 1) * 2 + 1];
            HMMA(acc[nf], a0, a1, a2, a3, b0, b1);
        }
    }

    // ---- write O ----------------------------------------------------------
    __half* o0 = out + (size_t)(w * 64 + i0) * DIMC + h * HD;
    __half* o1 = out + (size_t)(w * 64 + i1) * DIMC + h * HD;
    #pragma unroll
    for (int nf = 0; nf < 8; nf++) {
        int c = nf * 8 + q * 2;
        *(__half2*)(o0 + c) = __floats2half2_rn(acc[nf][0], acc[nf][1]);
        *(__half2*)(o1 + c) = __floats2half2_rn(acc[nf][2], acc[nf][3]);
    }
}

// ---------------- launch ---------------------------------------------------
extern "C" void kernel_launch(void* const* d_in, const int* in_sizes, int n_in,
                              void* d_out, int out_size)
{
    const float* x    = (const float*)d_in[0];
    const float* n1g  = (const float*)d_in[1];
    const float* n1b  = (const float*)d_in[2];
    const float* qkvw = (const float*)d_in[3];
    const float* qkvb = (const float*)d_in[4];
    const float* tab  = (const float*)d_in[5];
    const float* pw   = (const float*)d_in[6];
    const float* pb   = (const float*)d_in[7];
    const float* n2g  = (const float*)d_in[8];
    const float* n2b  = (const float*)d_in[9];
    const float* f1w  = (const float*)d_in[10];
    const float* f1b  = (const float*)d_in[11];
    const float* f2w  = (const float*)d_in[12];
    const float* f2b  = (const float*)d_in[13];
    float* out = (float*)d_out;

    __half *big, *hs, *oB, *wt;
    float *x2, *gb;
    cudaGetSymbolAddress((void**)&big, g_big);
    cudaGetSymbolAddress((void**)&hs,  g_hs);
    cudaGetSymbolAddress((void**)&oB,  g_o);
    cudaGetSymbolAddress((void**)&x2,  g_x2);
    cudaGetSymbolAddress((void**)&wt,  g_wt);
    cudaGetSymbolAddress((void**)&gb,  g_bias);
    __half* qkvB = big;
    __half* mid  = big;

    static int smem_set = 0;
    if (!smem_set) {
        cudaFuncSetAttribute(hgemm<0>, cudaFuncAttributeMaxDynamicSharedMemorySize, SMEM_GEMM);
        cudaFuncSetAttribute(hgemm<1>, cudaFuncAttributeMaxDynamicSharedMemorySize, SMEM_GEMM);
        cudaFuncSetAttribute(hgemm<2>, cudaFuncAttributeMaxDynamicSharedMemorySize, SMEM_GEMM);
        cudaFuncSetAttribute(hgemm<3>, cudaFuncAttributeMaxDynamicSharedMemorySize, SMEM_GEMM);
        smem_set = 1;
    }

    // precompute rel-pos bias matrix + weight fp16 pre-convert
    bias_kernel<<<(HEADS * 4096 + 255) / 256, 256>>>(tab, gb);
    {
        int n4 = W_TOT / 4;
        cvt_all_kernel<<<(n4 + 255) / 256, 256>>>(
            (const float4*)qkvw, (const float4*)pw,
            (const float4*)f1w,  (const float4*)f2w, wt);
    }

    // 1. LN1 + roll(-32)
    ln_kernel<<<M_ROWS / 8, 256>>>(x, n1g, n1b, hs, SHIFT);
    // 2. QKV projection (24576 x 2304 x 768)
    hgemm<0><<<dim3(2304 / 128, M_ROWS / 128), 128, SMEM_GEMM>>>(
        hs, wt + W_QKV, qkvb, nullptr, qkvB, M_ROWS, 3 * DIMC, DIMC);
    // 3. windowed attention (tensor-core)
    attn_kernel<<<dim3(BATCH * NWIN, HEADS), 128>>>(qkvB, gb, oB);
    // 4. proj + roll(+32) + residual -> x2
    hgemm<3><<<dim3(DIMC / 128, M_ROWS / 128), 128, SMEM_GEMM>>>(
        oB, wt + W_PROJ, pb, x, x2, M_ROWS, DIMC, DIMC);
    // 5. LN2
    ln_kernel<<<M_ROWS / 8, 256>>>(x2, n2g, n2b, hs, 0);
    // 6. fc1 + GELU (24576 x 3072 x 768)
    hgemm<1><<<dim3(3072 / 128, M_ROWS / 128), 128, SMEM_GEMM>>>(
        hs, wt + W_FC1, f1b, nullptr, mid, M_ROWS, 4 * DIMC, DIMC);
    // 7. fc2 + residual -> out (24576 x 768 x 3072)
    hgemm<2><<<dim3(DIMC / 128, M_ROWS / 128), 128, SMEM_GEMM>>>(
        mid, wt + W_FC2, f2b, x2, out, M_ROWS, DIMC, 4 * DIMC);
}